// round 16
// baseline (speedup 1.0000x reference)
#include <cuda_runtime.h>
#include <cuda_bf16.h>
#include <cstdint>
#include <math.h>

// Problem constants
#define B 2
#define NH 8
#define HH 48
#define WW 48
#define NSEQ (HH*WW)      // 2304
#define D 512
#define DPH 64
#define HALF 32
#define NROWS (B*NSEQ)    // 4608
#define QB 128            // q rows per attention CTA
#define KB 64             // keys per block
#define NKB (NSEQ/KB)     // 36

// Scratch (device globals; no allocation allowed)
#define NQKV ((size_t)B*NH*NSEQ*DPH)
__device__ __align__(16) __nv_bfloat16 g_xh[(size_t)NROWS*D], g_xl[(size_t)NROWS*D];
__device__ __align__(16) __nv_bfloat16 g_wth[(size_t)3*NH*DPH*D], g_wtl[(size_t)3*NH*DPH*D]; // [gz][h][v][k]
__device__ __align__(16) __nv_bfloat16 g_woth[(size_t)D*D], g_wotl[(size_t)D*D];             // [dd][h*64+v]
__device__ __align__(16) __nv_bfloat16 g_qh[NQKV], g_ql[NQKV];
__device__ __align__(16) __nv_bfloat16 g_kh[NQKV], g_kl[NQKV];
__device__ __align__(16) __nv_bfloat16 g_vth[NQKV], g_vtl[NQKV];  // [b][h][v][n]
__device__ __align__(16) __nv_bfloat16 g_oh[(size_t)NROWS*D], g_ol[(size_t)NROWS*D]; // [b][n][h*64+v]
__device__ __align__(8)  float2 g_cs[(size_t)NSEQ*HALF];          // [n][rc] = (cos, sin)

// ---------------------------------------------------------------------------
// helpers
// ---------------------------------------------------------------------------
__device__ __forceinline__ float exp2a(float x) {
    float y; asm("ex2.approx.f32 %0, %1;" : "=f"(y) : "f"(x)); return y;
}
__device__ __forceinline__ uint32_t smem_u32(const void* p) {
    uint32_t a;
    asm("{ .reg .u64 t; cvta.to.shared.u64 t, %1; cvt.u32.u64 %0, t; }"
        : "=r"(a) : "l"(p));
    return a;
}
__device__ __forceinline__ void cp16(uint32_t dst, const void* src) {
    asm volatile("cp.async.cg.shared.global [%0], [%1], 16;" :: "r"(dst), "l"(src));
}
#define CP_COMMIT() asm volatile("cp.async.commit_group;" ::: "memory")
#define CP_WAIT1()  asm volatile("cp.async.wait_group 1;" ::: "memory")
#define CP_WAIT0()  asm volatile("cp.async.wait_group 0;" ::: "memory")

// m16n8k16 bf16 mma, fp32 accumulate (baseline PTX, works on compute_103)
__device__ __forceinline__ void mma_bf16(float* c, const uint32_t* a,
                                         uint32_t b0, uint32_t b1) {
    asm volatile(
        "mma.sync.aligned.m16n8k16.row.col.f32.bf16.bf16.f32 "
        "{%0,%1,%2,%3}, {%4,%5,%6,%7}, {%8,%9}, {%0,%1,%2,%3};"
        : "+f"(c[0]), "+f"(c[1]), "+f"(c[2]), "+f"(c[3])
        : "r"(a[0]), "r"(a[1]), "r"(a[2]), "r"(a[3]), "r"(b0), "r"(b1));
}

// bf16 hi/lo split, RN (accurate; used in prep kernel)
__device__ __forceinline__ void split2(float a, float b, uint32_t& hi, uint32_t& lo) {
    __nv_bfloat16 ha = __float2bfloat16(a), hb = __float2bfloat16(b);
    float ra = a - __bfloat162float(ha), rb = b - __bfloat162float(hb);
    __nv_bfloat162 hv; hv.x = ha; hv.y = hb;
    __nv_bfloat162 lv; lv.x = __float2bfloat16(ra); lv.y = __float2bfloat16(rb);
    hi = *(uint32_t*)&hv; lo = *(uint32_t*)&lv;
}

// fast bf16 hi/lo split: hi = truncate (bit mask), lo = exact residual (bf16 RN).
__device__ __forceinline__ void split2f(float a, float b, uint32_t& hi, uint32_t& lo) {
    uint32_t ua = __float_as_uint(a), ub = __float_as_uint(b);
    hi = __byte_perm(ua, ub, 0x7632);          // {lo16 = hi(a), hi16 = hi(b)}
    float la = a - __uint_as_float(ua & 0xFFFF0000u);
    float lb = b - __uint_as_float(ub & 0xFFFF0000u);
    asm("cvt.rn.bf16x2.f32 %0, %1, %2;" : "=r"(lo) : "f"(lb), "f"(la));
}

// ---------------------------------------------------------------------------
// GEMM tile machinery (R12 config — best measured): CTA 128x128, 512 threads
// (4x4 warps, 32x32 warp tiles). smem/buffer 65536 B: AH @0, AL @16384,
// BH @32768, BL @49152. 3-stage ring (196608 B), lookahead-2, bunched loads.
// ---------------------------------------------------------------------------
#define GEMM_SMEM 196608

__device__ __forceinline__ void gemm_load128(uint32_t base, int tid, int k0,
    const __nv_bfloat16* __restrict__ ah, const __nv_bfloat16* __restrict__ al,
    const __nv_bfloat16* __restrict__ bh, const __nv_bfloat16* __restrict__ bl)
{
    #pragma unroll
    for (int i = 0; i < 8; ++i) {
        int idx = i * 512 + tid;
        int absel = idx >> 11;
        int hl = (idx >> 10) & 1;
        int j = idx & 1023;
        int r = j >> 3, c8 = j & 7;
        uint32_t dst = base + absel * 32768 + hl * 16384 + r * 128 +
                       ((c8 * 16) ^ ((r & 7) << 4));
        const __nv_bfloat16* src =
            (absel == 0) ? ((hl ? al : ah) + (size_t)r * D + k0 + c8 * 8)
                         : ((hl ? bl : bh) + (size_t)r * D + k0 + c8 * 8);
        cp16(dst, src);
    }
}

__device__ __forceinline__ void gemm_block128(const char* kb, int wm, int wn,
                                              int gr, int tq, float c[2][4][4])
{
    const uint32_t sw = (uint32_t)gr << 4;
    #pragma unroll
    for (int ks = 0; ks < 4; ++ks) {
        uint32_t cb = ks * 32 + tq * 4;
        uint32_t o0 = cb ^ sw, o1 = (cb + 16) ^ sw;
        uint32_t aH[2][4], aL[2][4];
        #pragma unroll
        for (int mf = 0; mf < 2; ++mf) {
            int row0 = wm * 32 + mf * 16 + gr;
            aH[mf][0] = *(const uint32_t*)(kb + row0 * 128 + o0);
            aH[mf][1] = *(const uint32_t*)(kb + (row0 + 8) * 128 + o0);
            aH[mf][2] = *(const uint32_t*)(kb + row0 * 128 + o1);
            aH[mf][3] = *(const uint32_t*)(kb + (row0 + 8) * 128 + o1);
            aL[mf][0] = *(const uint32_t*)(kb + 16384 + row0 * 128 + o0);
            aL[mf][1] = *(const uint32_t*)(kb + 16384 + (row0 + 8) * 128 + o0);
            aL[mf][2] = *(const uint32_t*)(kb + 16384 + row0 * 128 + o1);
            aL[mf][3] = *(const uint32_t*)(kb + 16384 + (row0 + 8) * 128 + o1);
        }
        #pragma unroll
        for (int nf = 0; nf < 4; ++nf) {
            int n = wn * 32 + nf * 8 + gr;
            uint32_t bh0 = *(const uint32_t*)(kb + 32768 + n * 128 + o0);
            uint32_t bh1 = *(const uint32_t*)(kb + 32768 + n * 128 + o1);
            uint32_t bl0 = *(const uint32_t*)(kb + 49152 + n * 128 + o0);
            uint32_t bl1 = *(const uint32_t*)(kb + 49152 + n * 128 + o1);
            #pragma unroll
            for (int mf = 0; mf < 2; ++mf) {
                mma_bf16(c[mf][nf], aH[mf], bh0, bh1);
                mma_bf16(c[mf][nf], aL[mf], bh0, bh1);
                mma_bf16(c[mf][nf], aH[mf], bl0, bl1);
            }
        }
    }
}

#define GEMM_MAINLOOP(AH, AL, BH, BL) \
    gemm_load128(smb, tid, 0, AH, AL, BH, BL); CP_COMMIT(); \
    gemm_load128(smb + 65536u, tid, 64, AH, AL, BH, BL); CP_COMMIT(); \
    _Pragma("unroll 1") \
    for (int kb = 0; kb < 8; ++kb) { \
        if (kb + 1 < 8) CP_WAIT1(); else CP_WAIT0(); \
        __syncthreads(); \
        if (kb + 2 < 8) { \
            gemm_load128(smb + (uint32_t)((kb + 2) % 3) * 65536u, tid, \
                         (kb + 2) * 64, AH, AL, BH, BL); \
            CP_COMMIT(); \
        } \
        gemm_block128(sm + (kb % 3) * 65536, wm, wn, gr, tq, c); \
    }

// ---------------------------------------------------------------------------
// Kernel 0: fused prep — weight transposes/splits + x split + RoPE cos/sin.
// grid (576, 6): y<4 transpose (x<512); y==4 splitx; y==5 cos/sin table.
// ---------------------------------------------------------------------------
__global__ __launch_bounds__(256) void prep_kernel(
    const float* __restrict__ x,
    const float* __restrict__ wq, const float* __restrict__ wk,
    const float* __restrict__ wv, const float* __restrict__ wo,
    const float* __restrict__ angles)
{
    const int which = blockIdx.y;
    if (which == 4) {
        int i0 = blockIdx.x * 256 + threadIdx.x;
        #pragma unroll
        for (int t = 0; t < 4; ++t) {
            size_t i = (size_t)(i0 + t * 147456) * 4;
            float4 v = *(const float4*)(x + i);
            uint32_t h0, l0, h1, l1;
            split2(v.x, v.y, h0, l0);
            split2(v.z, v.w, h1, l1);
            *(uint2*)(g_xh + i) = make_uint2(h0, h1);
            *(uint2*)(g_xl + i) = make_uint2(l0, l1);
        }
        return;
    }
    if (which == 5) {
        int idx = blockIdx.x * 256 + threadIdx.x;
        if (idx < NSEQ * HALF) {
            int n = idx >> 5, rc = idx & 31;
            int ii = n / WW, jj = n - (n / WW) * WW;
            float th = (float)ii * angles[rc] + (float)jj * angles[HALF + rc];
            float sn, cs;
            sincosf(th, &sn, &cs);
            g_cs[idx] = make_float2(cs, sn);
        }
        return;
    }
    const int k = blockIdx.x;
    if (k >= D) return;
    if (which < 3) {
        const float* __restrict__ w = (which == 0) ? wq : ((which == 1) ? wk : wv);
        for (int e = threadIdx.x; e < D; e += 256) {
            int v = e >> 3, h = e & 7;
            float val = w[(size_t)k * D + e];
            __nv_bfloat16 hv = __float2bfloat16(val);
            __nv_bfloat16 lv = __float2bfloat16(val - __bfloat162float(hv));
            size_t idx = (((size_t)which * NH + h) * DPH + v) * D + k;
            g_wth[idx] = hv; g_wtl[idx] = lv;
        }
    } else {
        for (int e = threadIdx.x; e < D; e += 256) {
            int v = e >> 3, h = e & 7;
            float val = wo[(size_t)k * D + e];
            __nv_bfloat16 hv = __float2bfloat16(val);
            __nv_bfloat16 lv = __float2bfloat16(val - __bfloat162float(hv));
            size_t idx = (size_t)k * D + h * DPH + v;
            g_woth[idx] = hv; g_wotl[idx] = lv;
        }
    }
}

// ---------------------------------------------------------------------------
// Kernel 1: QKV projection + RoPE (table-based). M=128 x N=128 tile.
// grid (36, 4, 3), 512 threads.
// ---------------------------------------------------------------------------
__global__ __launch_bounds__(512, 1) void proj_kernel()
{
    extern __shared__ char sm[];
    const uint32_t smb = smem_u32(sm);
    const int tid  = threadIdx.x;
    const int wid  = tid >> 5;
    const int lane = tid & 31;
    const int gr   = lane >> 2;
    const int tq   = lane & 3;
    const int wm   = wid >> 2;
    const int wn   = wid & 3;
    const int m0 = blockIdx.x * 128;
    const int c0blk = blockIdx.y * 128;   // B-row block: heads {2y, 2y+1}
    const int gz = blockIdx.z;

    const __nv_bfloat16* ah = g_xh + (size_t)m0 * D;
    const __nv_bfloat16* al = g_xl + (size_t)m0 * D;
    const __nv_bfloat16* bh = g_wth + ((size_t)gz * NH * DPH + c0blk) * D;
    const __nv_bfloat16* bl = g_wtl + ((size_t)gz * NH * DPH + c0blk) * D;

    float c[2][4][4];
    #pragma unroll
    for (int mf = 0; mf < 2; ++mf)
        #pragma unroll
        for (int nf = 0; nf < 4; ++nf)
            #pragma unroll
            for (int j = 0; j < 4; ++j) c[mf][nf][j] = 0.0f;

    GEMM_MAINLOOP(ah, al, bh, bl);

    const int b  = m0 / NSEQ;
    const int nb = m0 - b * NSEQ;
    const float qscale = 1.4426950408889634f / 8.0f;

    if (gz < 2) {
        const float qs = (gz == 0) ? qscale : 1.0f;
        __nv_bfloat16* oh = (gz == 0) ? g_qh : g_kh;
        __nv_bfloat16* ol = (gz == 0) ? g_ql : g_kl;
        #pragma unroll
        for (int mf = 0; mf < 2; ++mf) {
            int n0r = nb + wm * 32 + mf * 16 + gr;
            int n1r = n0r + 8;
            #pragma unroll
            for (int nf = 0; nf < 4; ++nf) {
                int rg = c0blk + wn * 32 + nf * 8 + tq * 2;
                int h = rg >> 6, v = rg & 63;
                int rc = v >> 1;
                float2 cs0 = g_cs[n0r * HALF + rc];
                float2 cs1 = g_cs[n1r * HALF + rc];
                float q0 = (c[mf][nf][0] * cs0.x - c[mf][nf][1] * cs0.y) * qs;
                float q1 = (c[mf][nf][0] * cs0.y + c[mf][nf][1] * cs0.x) * qs;
                float q2 = (c[mf][nf][2] * cs1.x - c[mf][nf][3] * cs1.y) * qs;
                float q3 = (c[mf][nf][2] * cs1.y + c[mf][nf][3] * cs1.x) * qs;
                size_t bhz = (size_t)b * NH + h;
                size_t base0 = (bhz * NSEQ + n0r) * DPH + v;
                size_t base1 = (bhz * NSEQ + n1r) * DPH + v;
                uint32_t h0, l0, h1, l1;
                split2f(q0, q1, h0, l0);
                split2f(q2, q3, h1, l1);
                *(uint32_t*)(oh + base0) = h0;
                *(uint32_t*)(ol + base0) = l0;
                *(uint32_t*)(oh + base1) = h1;
                *(uint32_t*)(ol + base1) = l1;
            }
        }
    } else {
        // V: stage fp32 tile transposed in smem [128 cols][132], then write
        float* smV = (float*)sm;
        __syncthreads();
        #pragma unroll
        for (int mf = 0; mf < 2; ++mf) {
            int r0 = wm * 32 + mf * 16 + gr;
            #pragma unroll
            for (int nf = 0; nf < 4; ++nf) {
                int lc = wn * 32 + nf * 8 + tq * 2;
                smV[lc * 132 + r0]           = c[mf][nf][0];
                smV[(lc + 1) * 132 + r0]     = c[mf][nf][1];
                smV[lc * 132 + r0 + 8]       = c[mf][nf][2];
                smV[(lc + 1) * 132 + r0 + 8] = c[mf][nf][3];
            }
        }
        __syncthreads();
        int lc = tid >> 2;
        int ns = (tid & 3) * 32;
        int rg = c0blk + lc;
        int h = rg >> 6, v = rg & 63;
        size_t bhz = (size_t)b * NH + h;
        __nv_bfloat16* dsth = g_vth + (bhz * DPH + v) * NSEQ + nb + ns;
        __nv_bfloat16* dstl = g_vtl + (bhz * DPH + v) * NSEQ + nb + ns;
        #pragma unroll
        for (int j = 0; j < 32; j += 2) {
            float f0 = smV[lc * 132 + ns + j], f1 = smV[lc * 132 + ns + j + 1];
            uint32_t hi, lo;
            split2f(f0, f1, hi, lo);
            *(uint32_t*)(dsth + j) = hi;
            *(uint32_t*)(dstl + j) = lo;
        }
    }
}

// ---------------------------------------------------------------------------
// Kernel 2: flash attention (R12 config — best measured), mma.sync bf16x3,
// fixed-shift softmax. 4 warps x 32 q-rows, n-halves; 3-stage cp.async ring,
// bunched loads, 1 barrier per block. grid (18, 8, 2), 128 threads.
// ---------------------------------------------------------------------------
__global__ __launch_bounds__(128, 2) void attn_kernel()
{
    extern __shared__ char sm[];
    const uint32_t smb = smem_u32(sm);
    const int tid  = threadIdx.x;
    const int wid  = tid >> 5;
    const int lane = tid & 31;
    const int gr   = lane >> 2;
    const int tq   = lane & 3;
    const int n0 = blockIdx.x * QB;
    const int h  = blockIdx.y;
    const int b  = blockIdx.z;
    const size_t bh = (size_t)b * NH + h;

    const __nv_bfloat16* kh_b = g_kh + bh * NSEQ * DPH;
    const __nv_bfloat16* kl_b = g_kl + bh * NSEQ * DPH;
    const __nv_bfloat16* vh_b = g_vth + bh * (size_t)DPH * NSEQ;
    const __nv_bfloat16* vl_b = g_vtl + bh * (size_t)DPH * NSEQ;

    uint32_t aQh[2][4][4], aQl[2][4][4];
    #pragma unroll
    for (int mf = 0; mf < 2; ++mf) {
        const __nv_bfloat16* qh_p = g_qh + (bh * NSEQ + n0 + wid * 32 + mf * 16) * DPH;
        const __nv_bfloat16* ql_p = g_ql + (bh * NSEQ + n0 + wid * 32 + mf * 16) * DPH;
        #pragma unroll
        for (int ks = 0; ks < 4; ++ks) {
            int c0 = ks * 16 + tq * 2;
            aQh[mf][ks][0] = *(const uint32_t*)(qh_p + gr * 64 + c0);
            aQh[mf][ks][1] = *(const uint32_t*)(qh_p + (gr + 8) * 64 + c0);
            aQh[mf][ks][2] = *(const uint32_t*)(qh_p + gr * 64 + c0 + 8);
            aQh[mf][ks][3] = *(const uint32_t*)(qh_p + (gr + 8) * 64 + c0 + 8);
            aQl[mf][ks][0] = *(const uint32_t*)(ql_p + gr * 64 + c0);
            aQl[mf][ks][1] = *(const uint32_t*)(ql_p + (gr + 8) * 64 + c0);
            aQl[mf][ks][2] = *(const uint32_t*)(ql_p + gr * 64 + c0 + 8);
            aQl[mf][ks][3] = *(const uint32_t*)(ql_p + (gr + 8) * 64 + c0 + 8);
        }
    }

    float o[2][8][4];
    #pragma unroll
    for (int mf = 0; mf < 2; ++mf)
        #pragma unroll
        for (int nt = 0; nt < 8; ++nt)
            #pragma unroll
            for (int j = 0; j < 4; ++j) o[mf][nt][j] = 0.0f;
    float lv[2][2] = {{0.0f, 0.0f}, {0.0f, 0.0f}};

    #define ISSUE_BLOCK(bufidx, kbv) do { \
        uint32_t _base = smb + (uint32_t)(bufidx) * 32768u; \
        int _kb = (kbv); \
        _Pragma("unroll") \
        for (int _i = 0; _i < 16; ++_i) { \
            int _tile = _i >> 2; \
            int _sub = ((_i & 3) << 7) + tid; \
            int _r = _sub >> 3, _c = _sub & 7; \
            uint32_t _dst = _base + _tile * 8192 + _r * 128 + \
                            ((_c * 16) ^ ((_r & 7) << 4)); \
            const __nv_bfloat16* _src; \
            if (_tile == 0)      _src = kh_b + (size_t)(_kb * 64 + _r) * 64 + _c * 8; \
            else if (_tile == 1) _src = kl_b + (size_t)(_kb * 64 + _r) * 64 + _c * 8; \
            else if (_tile == 2) _src = vh_b + (size_t)_r * NSEQ + _kb * 64 + _c * 8; \
            else                 _src = vl_b + (size_t)_r * NSEQ + _kb * 64 + _c * 8; \
            cp16(_dst, _src); \
        } \
    } while (0)

    ISSUE_BLOCK(0, 0);
    CP_COMMIT();
    ISSUE_BLOCK(1, 1);
    CP_COMMIT();

    const uint32_t sw = (uint32_t)gr << 4;

    #pragma unroll 1
    for (int kb = 0; kb < NKB; ++kb) {
        if (kb + 1 < NKB) CP_WAIT1(); else CP_WAIT0();
        __syncthreads();

        if (kb + 2 < NKB) {
            int bi = kb + 2 - ((kb + 2) / 3) * 3;
            ISSUE_BLOCK(bi, kb + 2);
            CP_COMMIT();
        }

        const char* kbase = sm + (kb - (kb / 3) * 3) * 32768;

        #pragma unroll
        for (int half = 0; half < 2; ++half) {
            float s[2][4][4];
            #pragma unroll
            for (int mf = 0; mf < 2; ++mf)
                #pragma unroll
                for (int nt = 0; nt < 4; ++nt)
                    #pragma unroll
                    for (int j = 0; j < 4; ++j) s[mf][nt][j] = 0.0f;

            #pragma unroll
            for (int ks = 0; ks < 4; ++ks) {
                uint32_t cb = tq * 4 + ks * 32;
                uint32_t c0 = cb ^ sw, c1 = (cb + 16) ^ sw;
                #pragma unroll
                for (int nt = 0; nt < 4; ++nt) {
                    int row = (half * 4 + nt) * 8 + gr;
                    uint32_t o0 = row * 128 + c0;
                    uint32_t o1 = row * 128 + c1;
                    uint32_t bh0 = *(const uint32_t*)(kbase + o0);
                    uint32_t bh1 = *(const uint32_t*)(kbase + o1);
                    uint32_t bl0 = *(const uint32_t*)(kbase + 8192 + o0);
                    uint32_t bl1 = *(const uint32_t*)(kbase + 8192 + o1);
                    #pragma unroll
                    for (int mf = 0; mf < 2; ++mf) {
                        mma_bf16(s[mf][nt], aQh[mf][ks], bh0, bh1);
                        mma_bf16(s[mf][nt], aQl[mf][ks], bh0, bh1);
                        mma_bf16(s[mf][nt], aQh[mf][ks], bl0, bl1);
                    }
                }
            }

            #pragma unroll
            for (int mf = 0; mf < 2; ++mf)
                #pragma unroll
                for (int nt = 0; nt < 4; ++nt) {
                    float* sv = s[mf][nt];
                    sv[0] = exp2a(sv[0]); sv[1] = exp2a(sv[1]);
                    sv[2] = exp2a(sv[2]); sv[3] = exp2a(sv[3]);
                    lv[mf][0] += sv[0] + sv[1];
                    lv[mf][1] += sv[2] + sv[3];
                }

            #pragma unroll
            for (int pp = 0; pp < 2; ++pp) {
                int p = half * 2 + pp;
                uint32_t aPh[2][4], aPl[2][4];
                #pragma unroll
                for (int mf = 0; mf < 2; ++mf) {
                    split2f(s[mf][2*pp][0],   s[mf][2*pp][1],   aPh[mf][0], aPl[mf][0]);
                    split2f(s[mf][2*pp][2],   s[mf][2*pp][3],   aPh[mf][1], aPl[mf][1]);
                    split2f(s[mf][2*pp+1][0], s[mf][2*pp+1][1], aPh[mf][2], aPl[mf][2]);
                    split2f(s[mf][2*pp+1][2], s[mf][2*pp+1][3], aPh[mf][3], aPl[mf][3]);
                }
                uint32_t cb = tq * 4 + p * 32;
                uint32_t c0 = cb ^ sw, c1 = (cb + 16) ^ sw;
                #pragma unroll
                for (int nt = 0; nt < 8; ++nt) {
                    int row = nt * 8 + gr;
                    uint32_t o0 = row * 128 + c0;
                    uint32_t o1 = row * 128 + c1;
                    uint32_t vh0 = *(const uint32_t*)(kbase + 16384 + o0);
                    uint32_t vh1 = *(const uint32_t*)(kbase + 16384 + o1);
                    uint32_t vl0 = *(const uint32_t*)(kbase + 24576 + o0);
                    uint32_t vl1 = *(const uint32_t*)(kbase + 24576 + o1);
                    #pragma unroll
                    for (int mf = 0; mf < 2; ++mf) {
                        mma_bf16(o[mf][nt], aPh[mf], vh0, vh1);
                        mma_bf16(o[mf][nt], aPl[mf], vh0, vh1);
                        mma_bf16(o[mf][nt], aPh[mf], vl0, vl1);
                    }
                }
            }
        }
    }
    #undef ISSUE_BLOCK

    #pragma unroll
    for (int mf = 0; mf < 2; ++mf)
        #pragma unroll
        for (int i = 0; i < 2; ++i) {
            lv[mf][i] += __shfl_xor_sync(0xffffffffu, lv[mf][i], 1);
            lv[mf][i] += __shfl_xor_sync(0xffffffffu, lv[mf][i], 2);
        }

    #pragma unroll
    for (int mf = 0; mf < 2; ++mf) {
        float inv0 = 1.0f / lv[mf][0], inv1 = 1.0f / lv[mf][1];
        int row0 = n0 + wid * 32 + mf * 16 + gr;
        size_t off0 = ((size_t)b * NSEQ + row0) * D + h * DPH;
        size_t off1 = off0 + (size_t)8 * D;
        #pragma unroll
        for (int nt = 0; nt < 8; ++nt) {
            int col = nt * 8 + tq * 2;
            uint32_t hi, lo;
            split2f(o[mf][nt][0] * inv0, o[mf][nt][1] * inv0, hi, lo);
            *(uint32_t*)(g_oh + off0 + col) = hi;
            *(uint32_t*)(g_ol + off0 + col) = lo;
            split2f(o[mf][nt][2] * inv1, o[mf][nt][3] * inv1, hi, lo);
            *(uint32_t*)(g_oh + off1 + col) = hi;
            *(uint32_t*)(g_ol + off1 + col) = lo;
        }
    }
}

// ---------------------------------------------------------------------------
// Kernel 3: output projection. M=128 x N=128 tile. grid (36, 4), 512 threads.
// ---------------------------------------------------------------------------
__global__ __launch_bounds__(512, 1) void outproj_kernel(float* __restrict__ out)
{
    extern __shared__ char sm[];
    const uint32_t smb = smem_u32(sm);
    const int tid  = threadIdx.x;
    const int wid  = tid >> 5;
    const int lane = tid & 31;
    const int gr   = lane >> 2;
    const int tq   = lane & 3;
    const int wm   = wid >> 2;
    const int wn   = wid & 3;
    const int m0 = blockIdx.x * 128;
    const int c0blk = blockIdx.y * 128;

    const __nv_bfloat16* ah = g_oh + (size_t)m0 * D;
    const __nv_bfloat16* al = g_ol + (size_t)m0 * D;
    const __nv_bfloat16* bh = g_woth + (size_t)c0blk * D;
    const __nv_bfloat16* bl = g_wotl + (size_t)c0blk * D;

    float c[2][4][4];
    #pragma unroll
    for (int mf = 0; mf < 2; ++mf)
        #pragma unroll
        for (int nf = 0; nf < 4; ++nf)
            #pragma unroll
            for (int j = 0; j < 4; ++j) c[mf][nf][j] = 0.0f;

    GEMM_MAINLOOP(ah, al, bh, bl);

    #pragma unroll
    for (int mf = 0; mf < 2; ++mf) {
        int grow0 = m0 + wm * 32 + mf * 16 + gr;
        #pragma unroll
        for (int nf = 0; nf < 4; ++nf) {
            int col = c0blk + wn * 32 + nf * 8 + tq * 2;
            *(float2*)(out + (size_t)grow0 * D + col) =
                make_float2(c[mf][nf][0], c[mf][nf][1]);
            *(float2*)(out + (size_t)(grow0 + 8) * D + col) =
                make_float2(c[mf][nf][2], c[mf][nf][3]);
        }
    }
}

// ---------------------------------------------------------------------------
extern "C" void kernel_launch(void* const* d_in, const int* in_sizes, int n_in,
                              void* d_out, int out_size)
{
    const float* x      = (const float*)d_in[0];
    const float* wq     = (const float*)d_in[1];
    const float* wk     = (const float*)d_in[2];
    const float* wv     = (const float*)d_in[3];
    const float* wo     = (const float*)d_in[4];
    const float* angles = (const float*)d_in[5];
    float* out = (float*)d_out;

    cudaFuncSetAttribute(proj_kernel,
                         cudaFuncAttributeMaxDynamicSharedMemorySize, GEMM_SMEM);
    cudaFuncSetAttribute(outproj_kernel,
                         cudaFuncAttributeMaxDynamicSharedMemorySize, GEMM_SMEM);
    cudaFuncSetAttribute(attn_kernel,
                         cudaFuncAttributeMaxDynamicSharedMemorySize, 98304);

    prep_kernel<<<dim3(576, 6), 256>>>(x, wq, wk, wv, wo, angles);
    proj_kernel<<<dim3(NROWS / 128, D / 128, 3), 512, GEMM_SMEM>>>();
    attn_kernel<<<dim3(NSEQ / QB, NH, B), 128, 98304>>>();
    outproj_kernel<<<dim3(NROWS / 128, D / 128), 512, GEMM_SMEM>>>(out);
}

// round 17
// speedup vs baseline: 1.0096x; 1.0096x over previous
#include <cuda_runtime.h>
#include <cuda_bf16.h>
#include <cstdint>
#include <math.h>

// Problem constants
#define B 2
#define NH 8
#define HH 48
#define WW 48
#define NSEQ (HH*WW)      // 2304
#define D 512
#define DPH 64
#define HALF 32
#define NROWS (B*NSEQ)    // 4608
#define QB 128            // q rows per attention CTA
#define KB 64             // keys per block
#define NKB (NSEQ/KB)     // 36

// Scratch (device globals; no allocation allowed)
#define NQKV ((size_t)B*NH*NSEQ*DPH)
__device__ __align__(16) __nv_bfloat16 g_xh[(size_t)NROWS*D], g_xl[(size_t)NROWS*D];
__device__ __align__(16) __nv_bfloat16 g_wth[(size_t)3*NH*DPH*D], g_wtl[(size_t)3*NH*DPH*D]; // [gz][h][v][k]
__device__ __align__(16) __nv_bfloat16 g_woth[(size_t)D*D], g_wotl[(size_t)D*D];             // [dd][h*64+v]
__device__ __align__(16) __nv_bfloat16 g_qh[NQKV], g_ql[NQKV];
__device__ __align__(16) __nv_bfloat16 g_kh[NQKV], g_kl[NQKV];
__device__ __align__(16) __nv_bfloat16 g_vth[NQKV], g_vtl[NQKV];  // [b][h][v][n]
__device__ __align__(16) __nv_bfloat16 g_oh[(size_t)NROWS*D], g_ol[(size_t)NROWS*D]; // [b][n][h*64+v]

// ---------------------------------------------------------------------------
// helpers
// ---------------------------------------------------------------------------
__device__ __forceinline__ float exp2a(float x) {
    float y; asm("ex2.approx.f32 %0, %1;" : "=f"(y) : "f"(x)); return y;
}
__device__ __forceinline__ uint32_t smem_u32(const void* p) {
    uint32_t a;
    asm("{ .reg .u64 t; cvta.to.shared.u64 t, %1; cvt.u32.u64 %0, t; }"
        : "=r"(a) : "l"(p));
    return a;
}
__device__ __forceinline__ void cp16(uint32_t dst, const void* src) {
    asm volatile("cp.async.cg.shared.global [%0], [%1], 16;" :: "r"(dst), "l"(src));
}
#define CP_COMMIT() asm volatile("cp.async.commit_group;" ::: "memory")
#define CP_WAIT1()  asm volatile("cp.async.wait_group 1;" ::: "memory")
#define CP_WAIT0()  asm volatile("cp.async.wait_group 0;" ::: "memory")

// m16n8k16 bf16 mma, fp32 accumulate (baseline PTX, works on compute_103)
__device__ __forceinline__ void mma_bf16(float* c, const uint32_t* a,
                                         uint32_t b0, uint32_t b1) {
    asm volatile(
        "mma.sync.aligned.m16n8k16.row.col.f32.bf16.bf16.f32 "
        "{%0,%1,%2,%3}, {%4,%5,%6,%7}, {%8,%9}, {%0,%1,%2,%3};"
        : "+f"(c[0]), "+f"(c[1]), "+f"(c[2]), "+f"(c[3])
        : "r"(a[0]), "r"(a[1]), "r"(a[2]), "r"(a[3]), "r"(b0), "r"(b1));
}

// bf16 hi/lo split, RN (accurate; used in prep kernel)
__device__ __forceinline__ void split2(float a, float b, uint32_t& hi, uint32_t& lo) {
    __nv_bfloat16 ha = __float2bfloat16(a), hb = __float2bfloat16(b);
    float ra = a - __bfloat162float(ha), rb = b - __bfloat162float(hb);
    __nv_bfloat162 hv; hv.x = ha; hv.y = hb;
    __nv_bfloat162 lv; lv.x = __float2bfloat16(ra); lv.y = __float2bfloat16(rb);
    hi = *(uint32_t*)&hv; lo = *(uint32_t*)&lv;
}

// fast bf16 hi/lo split: hi = truncate (bit mask), lo = exact residual (bf16 RN).
__device__ __forceinline__ void split2f(float a, float b, uint32_t& hi, uint32_t& lo) {
    uint32_t ua = __float_as_uint(a), ub = __float_as_uint(b);
    hi = __byte_perm(ua, ub, 0x7632);          // {lo16 = hi(a), hi16 = hi(b)}
    float la = a - __uint_as_float(ua & 0xFFFF0000u);
    float lb = b - __uint_as_float(ub & 0xFFFF0000u);
    asm("cvt.rn.bf16x2.f32 %0, %1, %2;" : "=r"(lo) : "f"(lb), "f"(la));
}

// ---------------------------------------------------------------------------
// GEMM tile machinery: M=128, N=128, K=64 per chunk, 512 threads (4x4 warps).
// smem per buffer (65536 B): AH @0, AL @16384, BH @32768, BL @49152.
// 3-stage cp.async ring (196608 B total), 1 CTA/SM, lookahead-2.
// ---------------------------------------------------------------------------
#define GEMM_SMEM 196608

__device__ __forceinline__ void gemm_load128(uint32_t base, int tid, int k0,
    const __nv_bfloat16* __restrict__ ah, const __nv_bfloat16* __restrict__ al,
    const __nv_bfloat16* __restrict__ bh, const __nv_bfloat16* __restrict__ bl)
{
    // 4 tiles x 128 rows x 8 chunks(16B) = 4096 chunks / 512 threads = 8 each
    #pragma unroll
    for (int i = 0; i < 8; ++i) {
        int idx = i * 512 + tid;
        int absel = idx >> 11;              // 0 = A, 1 = B
        int hl = (idx >> 10) & 1;
        int j = idx & 1023;
        int r = j >> 3, c8 = j & 7;
        uint32_t dst = base + absel * 32768 + hl * 16384 + r * 128 +
                       ((c8 * 16) ^ ((r & 7) << 4));
        const __nv_bfloat16* src =
            (absel == 0) ? ((hl ? al : ah) + (size_t)r * D + k0 + c8 * 8)
                         : ((hl ? bl : bh) + (size_t)r * D + k0 + c8 * 8);
        cp16(dst, src);
    }
}

__device__ __forceinline__ void gemm_block128(const char* kb, int wm, int wn,
                                              int gr, int tq, float c[2][4][4])
{
    const uint32_t sw = (uint32_t)gr << 4;
    #pragma unroll
    for (int ks = 0; ks < 4; ++ks) {
        uint32_t cb = ks * 32 + tq * 4;
        uint32_t o0 = cb ^ sw, o1 = (cb + 16) ^ sw;
        uint32_t aH[2][4], aL[2][4];
        #pragma unroll
        for (int mf = 0; mf < 2; ++mf) {
            int row0 = wm * 32 + mf * 16 + gr;
            aH[mf][0] = *(const uint32_t*)(kb + row0 * 128 + o0);
            aH[mf][1] = *(const uint32_t*)(kb + (row0 + 8) * 128 + o0);
            aH[mf][2] = *(const uint32_t*)(kb + row0 * 128 + o1);
            aH[mf][3] = *(const uint32_t*)(kb + (row0 + 8) * 128 + o1);
            aL[mf][0] = *(const uint32_t*)(kb + 16384 + row0 * 128 + o0);
            aL[mf][1] = *(const uint32_t*)(kb + 16384 + (row0 + 8) * 128 + o0);
            aL[mf][2] = *(const uint32_t*)(kb + 16384 + row0 * 128 + o1);
            aL[mf][3] = *(const uint32_t*)(kb + 16384 + (row0 + 8) * 128 + o1);
        }
        #pragma unroll
        for (int nf = 0; nf < 4; ++nf) {
            int n = wn * 32 + nf * 8 + gr;
            uint32_t bh0 = *(const uint32_t*)(kb + 32768 + n * 128 + o0);
            uint32_t bh1 = *(const uint32_t*)(kb + 32768 + n * 128 + o1);
            uint32_t bl0 = *(const uint32_t*)(kb + 49152 + n * 128 + o0);
            uint32_t bl1 = *(const uint32_t*)(kb + 49152 + n * 128 + o1);
            #pragma unroll
            for (int mf = 0; mf < 2; ++mf) {
                mma_bf16(c[mf][nf], aH[mf], bh0, bh1);
                mma_bf16(c[mf][nf], aL[mf], bh0, bh1);
                mma_bf16(c[mf][nf], aH[mf], bl0, bl1);
            }
        }
    }
}

// shared GEMM mainloop (8 K-chunks, 3-stage ring, lookahead-2)
#define GEMM_MAINLOOP(AH, AL, BH, BL) \
    gemm_load128(smb, tid, 0, AH, AL, BH, BL); CP_COMMIT(); \
    gemm_load128(smb + 65536u, tid, 64, AH, AL, BH, BL); CP_COMMIT(); \
    _Pragma("unroll 1") \
    for (int kb = 0; kb < 8; ++kb) { \
        if (kb + 1 < 8) CP_WAIT1(); else CP_WAIT0(); \
        __syncthreads(); \
        if (kb + 2 < 8) { \
            gemm_load128(smb + (uint32_t)((kb + 2) % 3) * 65536u, tid, \
                         (kb + 2) * 64, AH, AL, BH, BL); \
            CP_COMMIT(); \
        } \
        gemm_block128(sm + (kb % 3) * 65536, wm, wn, gr, tq, c); \
    }

// ---------------------------------------------------------------------------
// Kernel 0: fused prep — weight transposes/splits + x split.
// grid (576, 5): y<4 -> transpose lanes (x<512 active); y==4 -> splitx.
// ---------------------------------------------------------------------------
__global__ __launch_bounds__(256) void prep_kernel(
    const float* __restrict__ x,
    const float* __restrict__ wq, const float* __restrict__ wk,
    const float* __restrict__ wv, const float* __restrict__ wo)
{
    const int which = blockIdx.y;
    if (which == 4) {
        int i0 = blockIdx.x * 256 + threadIdx.x;
        #pragma unroll
        for (int t = 0; t < 4; ++t) {
            size_t i = (size_t)(i0 + t * 147456) * 4;
            float4 v = *(const float4*)(x + i);
            uint32_t h0, l0, h1, l1;
            split2(v.x, v.y, h0, l0);
            split2(v.z, v.w, h1, l1);
            *(uint2*)(g_xh + i) = make_uint2(h0, h1);
            *(uint2*)(g_xl + i) = make_uint2(l0, l1);
        }
        return;
    }
    const int k = blockIdx.x;
    if (k >= D) return;
    if (which < 3) {
        const float* __restrict__ w = (which == 0) ? wq : ((which == 1) ? wk : wv);
        for (int e = threadIdx.x; e < D; e += 256) {
            int v = e >> 3, h = e & 7;
            float val = w[(size_t)k * D + e];
            __nv_bfloat16 hv = __float2bfloat16(val);
            __nv_bfloat16 lv = __float2bfloat16(val - __bfloat162float(hv));
            size_t idx = (((size_t)which * NH + h) * DPH + v) * D + k;
            g_wth[idx] = hv; g_wtl[idx] = lv;
        }
    } else {
        for (int e = threadIdx.x; e < D; e += 256) {
            int v = e >> 3, h = e & 7;
            float val = wo[(size_t)k * D + e];
            __nv_bfloat16 hv = __float2bfloat16(val);
            __nv_bfloat16 lv = __float2bfloat16(val - __bfloat162float(hv));
            size_t idx = (size_t)k * D + h * DPH + v;
            g_woth[idx] = hv; g_wotl[idx] = lv;
        }
    }
}

// ---------------------------------------------------------------------------
// Kernel 1: QKV projection + RoPE. M=128 x N=128 tile (2 heads per CTA).
// grid (36, 4, 3), 512 threads.
// ---------------------------------------------------------------------------
__global__ __launch_bounds__(512, 1) void proj_kernel(const float* __restrict__ angles)
{
    extern __shared__ char sm[];
    const uint32_t smb = smem_u32(sm);
    const int tid  = threadIdx.x;
    const int wid  = tid >> 5;
    const int lane = tid & 31;
    const int gr   = lane >> 2;
    const int tq   = lane & 3;
    const int wm   = wid >> 2;
    const int wn   = wid & 3;
    const int m0 = blockIdx.x * 128;
    const int c0blk = blockIdx.y * 128;   // B-row block: heads {2y, 2y+1}
    const int gz = blockIdx.z;

    const __nv_bfloat16* ah = g_xh + (size_t)m0 * D;
    const __nv_bfloat16* al = g_xl + (size_t)m0 * D;
    const __nv_bfloat16* bh = g_wth + ((size_t)gz * NH * DPH + c0blk) * D;
    const __nv_bfloat16* bl = g_wtl + ((size_t)gz * NH * DPH + c0blk) * D;

    float c[2][4][4];
    #pragma unroll
    for (int mf = 0; mf < 2; ++mf)
        #pragma unroll
        for (int nf = 0; nf < 4; ++nf)
            #pragma unroll
            for (int j = 0; j < 4; ++j) c[mf][nf][j] = 0.0f;

    GEMM_MAINLOOP(ah, al, bh, bl);

    const int b  = m0 / NSEQ;
    const int nb = m0 - b * NSEQ;
    const float qscale = 1.4426950408889634f / 8.0f;

    if (gz < 2) {
        const float qs = (gz == 0) ? qscale : 1.0f;
        __nv_bfloat16* oh = (gz == 0) ? g_qh : g_kh;
        __nv_bfloat16* ol = (gz == 0) ? g_ql : g_kl;
        #pragma unroll
        for (int mf = 0; mf < 2; ++mf) {
            int n0r = nb + wm * 32 + mf * 16 + gr;
            int n1r = n0r + 8;
            int ii0 = n0r / WW, jj0 = n0r % WW;
            int ii1 = n1r / WW, jj1 = n1r % WW;
            #pragma unroll
            for (int nf = 0; nf < 4; ++nf) {
                int rg = c0blk + wn * 32 + nf * 8 + tq * 2;
                int h = rg >> 6, v = rg & 63;
                int rc = v >> 1;
                float a1 = angles[rc], a2 = angles[HALF + rc];
                float sn0, cs0, sn1, cs1;
                __sincosf((float)ii0 * a1 + (float)jj0 * a2, &sn0, &cs0);
                __sincosf((float)ii1 * a1 + (float)jj1 * a2, &sn1, &cs1);
                float q0 = (c[mf][nf][0] * cs0 - c[mf][nf][1] * sn0) * qs;
                float q1 = (c[mf][nf][0] * sn0 + c[mf][nf][1] * cs0) * qs;
                float q2 = (c[mf][nf][2] * cs1 - c[mf][nf][3] * sn1) * qs;
                float q3 = (c[mf][nf][2] * sn1 + c[mf][nf][3] * cs1) * qs;
                size_t bhz = (size_t)b * NH + h;
                size_t base0 = (bhz * NSEQ + n0r) * DPH + v;
                size_t base1 = (bhz * NSEQ + n1r) * DPH + v;
                uint32_t h0, l0, h1, l1;
                split2f(q0, q1, h0, l0);
                split2f(q2, q3, h1, l1);
                *(uint32_t*)(oh + base0) = h0;
                *(uint32_t*)(ol + base0) = l0;
                *(uint32_t*)(oh + base1) = h1;
                *(uint32_t*)(ol + base1) = l1;
            }
        }
    } else {
        // V: stage fp32 tile transposed in smem [128 cols][132], then write
        float* smV = (float*)sm;
        __syncthreads();   // gemm reads of last buffer done by all warps
        #pragma unroll
        for (int mf = 0; mf < 2; ++mf) {
            int r0 = wm * 32 + mf * 16 + gr;
            #pragma unroll
            for (int nf = 0; nf < 4; ++nf) {
                int lc = wn * 32 + nf * 8 + tq * 2;
                smV[lc * 132 + r0]           = c[mf][nf][0];
                smV[(lc + 1) * 132 + r0]     = c[mf][nf][1];
                smV[lc * 132 + r0 + 8]       = c[mf][nf][2];
                smV[(lc + 1) * 132 + r0 + 8] = c[mf][nf][3];
            }
        }
        __syncthreads();
        int lc = tid >> 2;               // local col 0..127
        int ns = (tid & 3) * 32;
        int rg = c0blk + lc;
        int h = rg >> 6, v = rg & 63;
        size_t bhz = (size_t)b * NH + h;
        __nv_bfloat16* dsth = g_vth + (bhz * DPH + v) * NSEQ + nb + ns;
        __nv_bfloat16* dstl = g_vtl + (bhz * DPH + v) * NSEQ + nb + ns;
        #pragma unroll
        for (int j = 0; j < 32; j += 2) {
            float f0 = smV[lc * 132 + ns + j], f1 = smV[lc * 132 + ns + j + 1];
            uint32_t hi, lo;
            split2f(f0, f1, hi, lo);
            *(uint32_t*)(dsth + j) = hi;
            *(uint32_t*)(dstl + j) = lo;
        }
    }
}

// ---------------------------------------------------------------------------
// Kernel 2: flash attention (best measured config), mma.sync bf16x3,
// fixed-shift softmax. 4 warps x 32 q-rows, n-halves.
// grid (18, 8, 2), 128 threads, 3-stage cp.async ring, 1 barrier per block.
// ---------------------------------------------------------------------------
__global__ __launch_bounds__(128, 2) void attn_kernel()
{
    extern __shared__ char sm[];
    const uint32_t smb = smem_u32(sm);
    const int tid  = threadIdx.x;
    const int wid  = tid >> 5;
    const int lane = tid & 31;
    const int gr   = lane >> 2;
    const int tq   = lane & 3;
    const int n0 = blockIdx.x * QB;
    const int h  = blockIdx.y;
    const int b  = blockIdx.z;
    const size_t bh = (size_t)b * NH + h;

    const __nv_bfloat16* kh_b = g_kh + bh * NSEQ * DPH;
    const __nv_bfloat16* kl_b = g_kl + bh * NSEQ * DPH;
    const __nv_bfloat16* vh_b = g_vth + bh * (size_t)DPH * NSEQ;
    const __nv_bfloat16* vl_b = g_vtl + bh * (size_t)DPH * NSEQ;

    uint32_t aQh[2][4][4], aQl[2][4][4];
    #pragma unroll
    for (int mf = 0; mf < 2; ++mf) {
        const __nv_bfloat16* qh_p = g_qh + (bh * NSEQ + n0 + wid * 32 + mf * 16) * DPH;
        const __nv_bfloat16* ql_p = g_ql + (bh * NSEQ + n0 + wid * 32 + mf * 16) * DPH;
        #pragma unroll
        for (int ks = 0; ks < 4; ++ks) {
            int c0 = ks * 16 + tq * 2;
            aQh[mf][ks][0] = *(const uint32_t*)(qh_p + gr * 64 + c0);
            aQh[mf][ks][1] = *(const uint32_t*)(qh_p + (gr + 8) * 64 + c0);
            aQh[mf][ks][2] = *(const uint32_t*)(qh_p + gr * 64 + c0 + 8);
            aQh[mf][ks][3] = *(const uint32_t*)(qh_p + (gr + 8) * 64 + c0 + 8);
            aQl[mf][ks][0] = *(const uint32_t*)(ql_p + gr * 64 + c0);
            aQl[mf][ks][1] = *(const uint32_t*)(ql_p + (gr + 8) * 64 + c0);
            aQl[mf][ks][2] = *(const uint32_t*)(ql_p + gr * 64 + c0 + 8);
            aQl[mf][ks][3] = *(const uint32_t*)(ql_p + (gr + 8) * 64 + c0 + 8);
        }
    }

    float o[2][8][4];
    #pragma unroll
    for (int mf = 0; mf < 2; ++mf)
        #pragma unroll
        for (int nt = 0; nt < 8; ++nt)
            #pragma unroll
            for (int j = 0; j < 4; ++j) o[mf][nt][j] = 0.0f;
    float lv[2][2] = {{0.0f, 0.0f}, {0.0f, 0.0f}};

    #define ISSUE_BLOCK(bufidx, kbv) do { \
        uint32_t _base = smb + (uint32_t)(bufidx) * 32768u; \
        int _kb = (kbv); \
        _Pragma("unroll") \
        for (int _i = 0; _i < 16; ++_i) { \
            int _tile = _i >> 2; \
            int _sub = ((_i & 3) << 7) + tid; \
            int _r = _sub >> 3, _c = _sub & 7; \
            uint32_t _dst = _base + _tile * 8192 + _r * 128 + \
                            ((_c * 16) ^ ((_r & 7) << 4)); \
            const __nv_bfloat16* _src; \
            if (_tile == 0)      _src = kh_b + (size_t)(_kb * 64 + _r) * 64 + _c * 8; \
            else if (_tile == 1) _src = kl_b + (size_t)(_kb * 64 + _r) * 64 + _c * 8; \
            else if (_tile == 2) _src = vh_b + (size_t)_r * NSEQ + _kb * 64 + _c * 8; \
            else                 _src = vl_b + (size_t)_r * NSEQ + _kb * 64 + _c * 8; \
            cp16(_dst, _src); \
        } \
    } while (0)

    ISSUE_BLOCK(0, 0);
    CP_COMMIT();
    ISSUE_BLOCK(1, 1);
    CP_COMMIT();

    const uint32_t sw = (uint32_t)gr << 4;

    #pragma unroll 1
    for (int kb = 0; kb < NKB; ++kb) {
        if (kb + 1 < NKB) CP_WAIT1(); else CP_WAIT0();
        __syncthreads();

        if (kb + 2 < NKB) {
            int bi = kb + 2 - ((kb + 2) / 3) * 3;
            ISSUE_BLOCK(bi, kb + 2);
            CP_COMMIT();
        }

        const char* kbase = sm + (kb - (kb / 3) * 3) * 32768;

        #pragma unroll
        for (int half = 0; half < 2; ++half) {
            float s[2][4][4];
            #pragma unroll
            for (int mf = 0; mf < 2; ++mf)
                #pragma unroll
                for (int nt = 0; nt < 4; ++nt)
                    #pragma unroll
                    for (int j = 0; j < 4; ++j) s[mf][nt][j] = 0.0f;

            #pragma unroll
            for (int ks = 0; ks < 4; ++ks) {
                uint32_t cb = tq * 4 + ks * 32;
                uint32_t c0 = cb ^ sw, c1 = (cb + 16) ^ sw;
                #pragma unroll
                for (int nt = 0; nt < 4; ++nt) {
                    int row = (half * 4 + nt) * 8 + gr;
                    uint32_t o0 = row * 128 + c0;
                    uint32_t o1 = row * 128 + c1;
                    uint32_t bh0 = *(const uint32_t*)(kbase + o0);
                    uint32_t bh1 = *(const uint32_t*)(kbase + o1);
                    uint32_t bl0 = *(const uint32_t*)(kbase + 8192 + o0);
                    uint32_t bl1 = *(const uint32_t*)(kbase + 8192 + o1);
                    #pragma unroll
                    for (int mf = 0; mf < 2; ++mf) {
                        mma_bf16(s[mf][nt], aQh[mf][ks], bh0, bh1);
                        mma_bf16(s[mf][nt], aQl[mf][ks], bh0, bh1);
                        mma_bf16(s[mf][nt], aQh[mf][ks], bl0, bl1);
                    }
                }
            }

            #pragma unroll
            for (int mf = 0; mf < 2; ++mf)
                #pragma unroll
                for (int nt = 0; nt < 4; ++nt) {
                    float* sv = s[mf][nt];
                    sv[0] = exp2a(sv[0]); sv[1] = exp2a(sv[1]);
                    sv[2] = exp2a(sv[2]); sv[3] = exp2a(sv[3]);
                    lv[mf][0] += sv[0] + sv[1];
                    lv[mf][1] += sv[2] + sv[3];
                }

            #pragma unroll
            for (int pp = 0; pp < 2; ++pp) {
                int p = half * 2 + pp;
                uint32_t aPh[2][4], aPl[2][4];
                #pragma unroll
                for (int mf = 0; mf < 2; ++mf) {
                    split2f(s[mf][2*pp][0],   s[mf][2*pp][1],   aPh[mf][0], aPl[mf][0]);
                    split2f(s[mf][2*pp][2],   s[mf][2*pp][3],   aPh[mf][1], aPl[mf][1]);
                    split2f(s[mf][2*pp+1][0], s[mf][2*pp+1][1], aPh[mf][2], aPl[mf][2]);
                    split2f(s[mf][2*pp+1][2], s[mf][2*pp+1][3], aPh[mf][3], aPl[mf][3]);
                }
                uint32_t cb = tq * 4 + p * 32;
                uint32_t c0 = cb ^ sw, c1 = (cb + 16) ^ sw;
                #pragma unroll
                for (int nt = 0; nt < 8; ++nt) {
                    int row = nt * 8 + gr;
                    uint32_t o0 = row * 128 + c0;
                    uint32_t o1 = row * 128 + c1;
                    uint32_t vh0 = *(const uint32_t*)(kbase + 16384 + o0);
                    uint32_t vh1 = *(const uint32_t*)(kbase + 16384 + o1);
                    uint32_t vl0 = *(const uint32_t*)(kbase + 24576 + o0);
                    uint32_t vl1 = *(const uint32_t*)(kbase + 24576 + o1);
                    #pragma unroll
                    for (int mf = 0; mf < 2; ++mf) {
                        mma_bf16(o[mf][nt], aPh[mf], vh0, vh1);
                        mma_bf16(o[mf][nt], aPl[mf], vh0, vh1);
                        mma_bf16(o[mf][nt], aPh[mf], vl0, vl1);
                    }
                }
            }
        }
    }
    #undef ISSUE_BLOCK

    #pragma unroll
    for (int mf = 0; mf < 2; ++mf)
        #pragma unroll
        for (int i = 0; i < 2; ++i) {
            lv[mf][i] += __shfl_xor_sync(0xffffffffu, lv[mf][i], 1);
            lv[mf][i] += __shfl_xor_sync(0xffffffffu, lv[mf][i], 2);
        }

    #pragma unroll
    for (int mf = 0; mf < 2; ++mf) {
        float inv0 = 1.0f / lv[mf][0], inv1 = 1.0f / lv[mf][1];
        int row0 = n0 + wid * 32 + mf * 16 + gr;
        size_t off0 = ((size_t)b * NSEQ + row0) * D + h * DPH;
        size_t off1 = off0 + (size_t)8 * D;
        #pragma unroll
        for (int nt = 0; nt < 8; ++nt) {
            int col = nt * 8 + tq * 2;
            uint32_t hi, lo;
            split2f(o[mf][nt][0] * inv0, o[mf][nt][1] * inv0, hi, lo);
            *(uint32_t*)(g_oh + off0 + col) = hi;
            *(uint32_t*)(g_ol + off0 + col) = lo;
            split2f(o[mf][nt][2] * inv1, o[mf][nt][3] * inv1, hi, lo);
            *(uint32_t*)(g_oh + off1 + col) = hi;
            *(uint32_t*)(g_ol + off1 + col) = lo;
        }
    }
}

// ---------------------------------------------------------------------------
// Kernel 3: output projection. M=128 x N=128 tile. grid (36, 4), 512 threads.
// ---------------------------------------------------------------------------
__global__ __launch_bounds__(512, 1) void outproj_kernel(float* __restrict__ out)
{
    extern __shared__ char sm[];
    const uint32_t smb = smem_u32(sm);
    const int tid  = threadIdx.x;
    const int wid  = tid >> 5;
    const int lane = tid & 31;
    const int gr   = lane >> 2;
    const int tq   = lane & 3;
    const int wm   = wid >> 2;
    const int wn   = wid & 3;
    const int m0 = blockIdx.x * 128;
    const int c0blk = blockIdx.y * 128;

    const __nv_bfloat16* ah = g_oh + (size_t)m0 * D;
    const __nv_bfloat16* al = g_ol + (size_t)m0 * D;
    const __nv_bfloat16* bh = g_woth + (size_t)c0blk * D;
    const __nv_bfloat16* bl = g_wotl + (size_t)c0blk * D;

    float c[2][4][4];
    #pragma unroll
    for (int mf = 0; mf < 2; ++mf)
        #pragma unroll
        for (int nf = 0; nf < 4; ++nf)
            #pragma unroll
            for (int j = 0; j < 4; ++j) c[mf][nf][j] = 0.0f;

    GEMM_MAINLOOP(ah, al, bh, bl);

    #pragma unroll
    for (int mf = 0; mf < 2; ++mf) {
        int grow0 = m0 + wm * 32 + mf * 16 + gr;
        #pragma unroll
        for (int nf = 0; nf < 4; ++nf) {
            int col = c0blk + wn * 32 + nf * 8 + tq * 2;
            *(float2*)(out + (size_t)grow0 * D + col) =
                make_float2(c[mf][nf][0], c[mf][nf][1]);
            *(float2*)(out + (size_t)(grow0 + 8) * D + col) =
                make_float2(c[mf][nf][2], c[mf][nf][3]);
        }
    }
}

// ---------------------------------------------------------------------------
extern "C" void kernel_launch(void* const* d_in, const int* in_sizes, int n_in,
                              void* d_out, int out_size)
{
    const float* x      = (const float*)d_in[0];
    const float* wq     = (const float*)d_in[1];
    const float* wk     = (const float*)d_in[2];
    const float* wv     = (const float*)d_in[3];
    const float* wo     = (const float*)d_in[4];
    const float* angles = (const float*)d_in[5];
    float* out = (float*)d_out;

    cudaFuncSetAttribute(proj_kernel,
                         cudaFuncAttributeMaxDynamicSharedMemorySize, GEMM_SMEM);
    cudaFuncSetAttribute(outproj_kernel,
                         cudaFuncAttributeMaxDynamicSharedMemorySize, GEMM_SMEM);
    cudaFuncSetAttribute(attn_kernel,
                         cudaFuncAttributeMaxDynamicSharedMemorySize, 98304);

    prep_kernel<<<dim3(576, 5), 256>>>(x, wq, wk, wv, wo);
    proj_kernel<<<dim3(NROWS / 128, D / 128, 3), 512, GEMM_SMEM>>>(angles);
    attn_kernel<<<dim3(NSEQ / QB, NH, B), 128, 98304>>>();
    outproj_kernel<<<dim3(NROWS / 128, D / 128), 512, GEMM_SMEM>>>(out);
}